// round 4
// baseline (speedup 1.0000x reference)
#include <cuda_runtime.h>
#include <cuda_fp16.h>
#include <math.h>

// Problem constants
#define B_   16
#define C_   256
#define NH_  8
#define HD_  32
#define N_   1024
#define M_   256
#define HID_ 24
#define EPS_ 1e-5f

// ---------------- scratch (static __device__, no allocs) ----------------
__device__ float  S_q[B_ * NH_ * N_ * HD_];        // fp32
__device__ float  S_k[B_ * NH_ * M_ * HD_];        // fp32
__device__ float  S_v[B_ * NH_ * M_ * HD_];        // fp32
__device__ __half S_attn[B_ * NH_ * N_ * M_];      // 67 MB half
__device__ __half S_y[B_ * HID_ * N_ * M_];        // 202 MB half
__device__ __half S_r[B_ * NH_ * N_ * M_];         // 67 MB half
__device__ float  S_hout[B_ * N_ * C_];            // fp32
__device__ float  S_stats1[B_ * 3 * 2];
__device__ float  S_stats2[B_ * 3 * 2];
__device__ float  S_stats3[B_ * 2];

__device__ __forceinline__ float wred(float v) {
#pragma unroll
    for (int o = 16; o; o >>= 1) v += __shfl_xor_sync(0xffffffffu, v, o);
    return v;
}
__device__ __forceinline__ float fsig(float x) {
    return __fdividef(1.f, 1.f + __expf(-x));
}

// ---------------- fused projections (q + kv) + stats zeroing ----------------
__global__ __launch_bounds__(256) void k_all_proj(
    const float* __restrict__ q, const float* __restrict__ Wq,
    const float* __restrict__ kv, const float* __restrict__ Wkv) {
    __shared__ float sbuf[8192];
    const int b = blockIdx.x;
    const int y = blockIdx.y;
    const int t = threadIdx.x;
    if (b == 0 && y == 0) {
        if (t < 96) { S_stats1[t] = 0.f; S_stats2[t] = 0.f; }
        if (t < 32) S_stats3[t] = 0.f;
    }
    if (y < 32) {
        // ---- q projection: n-tile of 32 ----
        const int n0 = y * 32;
        for (int idx = t; idx < 2048; idx += 256) {
            int c = idx >> 3, i4 = idx & 7;
            ((float4*)sbuf)[idx] = ((const float4*)(q + (b * 256 + c) * 1024 + n0))[i4];
        }
        __syncthreads();
        float acc[32];
#pragma unroll
        for (int i = 0; i < 32; i++) acc[i] = 0.f;
        const float* wrow = Wq + t * 256;
        for (int c = 0; c < 256; c++) {
            float w = __ldg(wrow + c);
            const float4* q4 = (const float4*)(sbuf + c * 32);
#pragma unroll
            for (int i4 = 0; i4 < 8; i4++) {
                float4 qq = q4[i4];
                acc[i4 * 4 + 0] += qq.x * w;
                acc[i4 * 4 + 1] += qq.y * w;
                acc[i4 * 4 + 2] += qq.z * w;
                acc[i4 * 4 + 3] += qq.w * w;
            }
        }
        int h = t >> 5, d = t & 31;
#pragma unroll
        for (int i = 0; i < 32; i++)
            S_q[((b * 8 + h) * 1024 + n0 + i) * 32 + d] = acc[i];
    } else {
        // ---- kv projection: m-tile of 16 ----
        const int m0 = (y - 32) * 16;
        for (int idx = t; idx < 4096; idx += 256) {
            int c = idx >> 4, i = idx & 15;
            sbuf[c * 16 + i] = kv[(b * 256 + c) * 256 + m0 + i];
        }
        __syncthreads();
        for (int jj = 0; jj < 2; jj++) {
            int j = t + jj * 256;
            float acc[16];
#pragma unroll
            for (int i = 0; i < 16; i++) acc[i] = 0.f;
            const float* wrow = Wkv + j * 256;
            for (int c = 0; c < 256; c++) {
                float w = __ldg(wrow + c);
                const float4* k4 = (const float4*)(sbuf + c * 16);
#pragma unroll
                for (int i4 = 0; i4 < 4; i4++) {
                    float4 kk = k4[i4];
                    acc[i4 * 4 + 0] += kk.x * w;
                    acc[i4 * 4 + 1] += kk.y * w;
                    acc[i4 * 4 + 2] += kk.z * w;
                    acc[i4 * 4 + 3] += kk.w * w;
                }
            }
            float* dst = (j < 256) ? S_k : S_v;
            int hd = j & 255;
            int h = hd >> 5, d = hd & 31;
#pragma unroll
            for (int i = 0; i < 16; i++)
                dst[((b * 8 + h) * 256 + m0 + i) * 32 + d] = acc[i];
        }
    }
}

// ---------------- attention: register-tiled QK^T + softmax -> half ----------------
__global__ __launch_bounds__(256) void k_attn(const float* __restrict__ rpb) {
    const int bh = blockIdx.x;
    const int n0 = blockIdx.y * 64;
    __shared__ float Qs[32 * 68];   // [k][n] stride 68
    __shared__ float Ks[32 * 260];  // [k][m] stride 260
    const int t = threadIdx.x;
    {
        const int d = t & 31, g = t >> 5;
        const float* qsrc = S_q + (size_t)(bh * 1024 + n0) * 32 + d;
#pragma unroll
        for (int i = 0; i < 8; i++)
            Qs[d * 68 + g * 8 + i] = qsrc[(g * 8 + i) * 32];
        const float* ksrc = S_k + (size_t)bh * 8192 + d;
#pragma unroll
        for (int i = 0; i < 32; i++)
            Ks[d * 260 + g * 32 + i] = ksrc[(g * 32 + i) * 32];
    }
    __syncthreads();
    const int mg = t & 31;   // 32 m-groups (8 cols each) — whole warp shares ng
    const int ng = t >> 5;   // 8 n-groups (8 rows each)
    float acc[8][8];
#pragma unroll
    for (int i = 0; i < 8; i++)
#pragma unroll
        for (int j = 0; j < 8; j++) acc[i][j] = 0.f;
#pragma unroll 4
    for (int k = 0; k < 32; k++) {
        float4 q0 = *(const float4*)&Qs[k * 68 + ng * 8];
        float4 q1 = *(const float4*)&Qs[k * 68 + ng * 8 + 4];
        float4 k0 = *(const float4*)&Ks[k * 260 + mg * 8];
        float4 k1 = *(const float4*)&Ks[k * 260 + mg * 8 + 4];
        float qv[8] = {q0.x, q0.y, q0.z, q0.w, q1.x, q1.y, q1.z, q1.w};
        float kw[8] = {k0.x, k0.y, k0.z, k0.w, k1.x, k1.y, k1.z, k1.w};
#pragma unroll
        for (int i = 0; i < 8; i++)
#pragma unroll
            for (int j = 0; j < 8; j++) acc[i][j] += qv[i] * kw[j];
    }
    const float scale = 0.17677669529663689f;  // 32^-0.5
#pragma unroll
    for (int i = 0; i < 8; i++) {
        const int n = n0 + ng * 8 + i;
        const float* rp = rpb + (size_t)n * 256 + mg * 8;
        float4 r0 = *(const float4*)rp;
        float4 r1 = *(const float4*)(rp + 4);
        float rb[8] = {r0.x, r0.y, r0.z, r0.w, r1.x, r1.y, r1.z, r1.w};
        float mx = -1e30f;
#pragma unroll
        for (int j = 0; j < 8; j++) {
            acc[i][j] = acc[i][j] * scale + rb[j];
            mx = fmaxf(mx, acc[i][j]);
        }
#pragma unroll
        for (int o = 16; o; o >>= 1) mx = fmaxf(mx, __shfl_xor_sync(0xffffffffu, mx, o));
        float s = 0.f;
#pragma unroll
        for (int j = 0; j < 8; j++) {
            float e = __expf(acc[i][j] - mx);
            acc[i][j] = e;
            s += e;
        }
        s = wred(s);
        float inv = __fdividef(1.f, s);
        union { uint4 u4; __half2 h2[4]; } pk;
#pragma unroll
        for (int j = 0; j < 4; j++)
            pk.h2[j] = __floats2half2_rn(acc[i][2 * j] * inv, acc[i][2 * j + 1] * inv);
        *(uint4*)(S_attn + (size_t)(bh * 1024 + n) * 256 + mg * 8) = pk.u4;
    }
}

// ---------------- GN1 statistics over x = W_exp @ attn (half2 reads) ----------------
__global__ __launch_bounds__(256) void k_stats1(const float* __restrict__ W_exp) {
    const int b = blockIdx.x;
    const int base2 = blockIdx.y * 4096;  // half2 index
    __shared__ float we[192];
    __shared__ float red[6];
    const int t = threadIdx.x;
    if (t < 192) we[t] = W_exp[t];
    if (t < 6) red[t] = 0.f;
    __syncthreads();
    float s0 = 0, s1 = 0, s2 = 0, q0 = 0, q1 = 0, q2 = 0;
    const __half2* A = (const __half2*)S_attn + (size_t)b * 1048576;
    for (int k = 0; k < 16; k++) {
        int p = base2 + k * 256 + t;
        float2 a[8];
#pragma unroll
        for (int h = 0; h < 8; h++) a[h] = __half22float2(A[h * 131072 + p]);
#pragma unroll
        for (int o = 0; o < 24; o++) {
            float x0 = 0.f, x1 = 0.f;
#pragma unroll
            for (int h = 0; h < 8; h++) {
                float w = we[o * 8 + h];
                x0 += w * a[h].x;
                x1 += w * a[h].y;
            }
            float s = x0 + x1, qq = x0 * x0 + x1 * x1;
            if (o < 8)       { s0 += s; q0 += qq; }
            else if (o < 16) { s1 += s; q1 += qq; }
            else             { s2 += s; q2 += qq; }
        }
    }
    s0 = wred(s0); q0 = wred(q0); s1 = wred(s1);
    q1 = wred(q1); s2 = wred(s2); q2 = wred(q2);
    if ((t & 31) == 0) {
        atomicAdd(&red[0], s0); atomicAdd(&red[1], q0);
        atomicAdd(&red[2], s1); atomicAdd(&red[3], q1);
        atomicAdd(&red[4], s2); atomicAdd(&red[5], q2);
    }
    __syncthreads();
    if (t < 6) atomicAdd(&S_stats1[b * 6 + t], red[t]);
}

// ---------------- DLA pass 0: expand->GN1->swish->dw3x3 -> store y(half) + GN2 stats ----------------
__global__ __launch_bounds__(256) void k_dla0(
    const float* __restrict__ W_exp, const float* __restrict__ g1,
    const float* __restrict__ b1, const float* __restrict__ W_dw) {
    const int m0 = blockIdx.x * 32;
    const int n0 = blockIdx.y * 16;
    const int b = blockIdx.z;
    extern __shared__ float xact[];  // 24 * 612 floats
    __shared__ float we[192], wd[216];
    __shared__ float g1s[24], b1s[24];
    __shared__ float mu1[3], rs1[3];
    __shared__ float red[6];
    const int t = threadIdx.x;
    if (t < 192) we[t] = W_exp[t];
    if (t < 216) wd[t] = W_dw[t];
    if (t < 24) { g1s[t] = g1[t]; b1s[t] = b1[t]; }
    if (t < 3) {
        const float cnt = 2097152.f;
        float s = S_stats1[b * 6 + 2 * t], qq = S_stats1[b * 6 + 2 * t + 1];
        float m = s / cnt;
        mu1[t] = m;
        rs1[t] = rsqrtf(qq / cnt - m * m + EPS_);
    }
    if (t < 6) red[t] = 0.f;
    __syncthreads();

    for (int idx = t; idx < 612; idx += 256) {
        int i = idx / 34, j = idx - i * 34;
        int gi = n0 - 1 + i, gj = m0 - 1 + j;
        if ((unsigned)gi < 1024u && (unsigned)gj < 256u) {
            const __half* A = S_attn + (size_t)b * 2097152 + gi * 256 + gj;
            float a[8];
#pragma unroll
            for (int h = 0; h < 8; h++) a[h] = __half2float(A[h * 262144]);
#pragma unroll
            for (int o = 0; o < 24; o++) {
                float x = 0.f;
#pragma unroll
                for (int h = 0; h < 8; h++) x += we[o * 8 + h] * a[h];
                int g = o >> 3;
                x = (x - mu1[g]) * rs1[g] * g1s[o] + b1s[o];
                x = x * fsig(x);
                xact[o * 612 + idx] = x;
            }
        } else {
#pragma unroll
            for (int o = 0; o < 24; o++) xact[o * 612 + idx] = 0.f;
        }
    }
    __syncthreads();

    float s0 = 0, s1 = 0, s2 = 0, q0 = 0, q1 = 0, q2 = 0;
    for (int k = 0; k < 2; k++) {
        int pixl = t + k * 256;
        int i = pixl >> 5, j = pixl & 31;
        size_t gp = (size_t)(n0 + i) * 256 + (m0 + j);
#pragma unroll
        for (int o = 0; o < 24; o++) {
            const float* xb = xact + o * 612 + i * 34 + j;
            const float* w = wd + o * 9;
            float y = w[0] * xb[0] + w[1] * xb[1] + w[2] * xb[2]
                    + w[3] * xb[34] + w[4] * xb[35] + w[5] * xb[36]
                    + w[6] * xb[68] + w[7] * xb[69] + w[8] * xb[70];
            S_y[((size_t)(b * 24 + o)) * 262144 + gp] = __float2half_rn(y);
            if (o < 8)       { s0 += y; q0 += y * y; }
            else if (o < 16) { s1 += y; q1 += y * y; }
            else             { s2 += y; q2 += y * y; }
        }
    }
    s0 = wred(s0); q0 = wred(q0); s1 = wred(s1);
    q1 = wred(q1); s2 = wred(s2); q2 = wred(q2);
    if ((t & 31) == 0) {
        atomicAdd(&red[0], s0); atomicAdd(&red[1], q0);
        atomicAdd(&red[2], s1); atomicAdd(&red[3], q1);
        atomicAdd(&red[4], s2); atomicAdd(&red[5], q2);
    }
    __syncthreads();
    if (t < 6) atomicAdd(&S_stats2[b * 6 + t], red[t]);
}

// ---------------- DLA pass 1: GN2->swish->1x1 reduce -> r(half) + GN3 stats (half2) ----------------
__global__ __launch_bounds__(256) void k_red(
    const float* __restrict__ g2, const float* __restrict__ b2,
    const float* __restrict__ W_red) {
    const int b = blockIdx.x;
    const int p0 = blockIdx.y * 1024;  // half2 index; grid.y = 128
    __shared__ float wrd[192], g2s[24], b2s[24];
    __shared__ float mu2[3], rs2[3];
    __shared__ float red[2];
    const int t = threadIdx.x;
    if (t < 192) wrd[t] = W_red[t];
    if (t < 24) { g2s[t] = g2[t]; b2s[t] = b2[t]; }
    if (t < 3) {
        const float cnt = 2097152.f;
        float s = S_stats2[b * 6 + 2 * t], qq = S_stats2[b * 6 + 2 * t + 1];
        float m = s / cnt;
        mu2[t] = m;
        rs2[t] = rsqrtf(qq / cnt - m * m + EPS_);
    }
    if (t < 2) red[t] = 0.f;
    __syncthreads();
    float s3 = 0, q3 = 0;
    const __half2* Y = (const __half2*)S_y + (size_t)(b * 24) * 131072;
    __half2* R = (__half2*)S_r + (size_t)(b * 8) * 131072;
#pragma unroll 2
    for (int k = 0; k < 4; k++) {
        int p = p0 + k * 256 + t;
        float r0[8], r1[8];
#pragma unroll
        for (int h = 0; h < 8; h++) { r0[h] = 0.f; r1[h] = 0.f; }
#pragma unroll
        for (int o = 0; o < 24; o++) {
            float2 yf = __half22float2(Y[(size_t)o * 131072 + p]);
            int g = o >> 3;
            float sc = rs2[g] * g2s[o];
            float z0 = (yf.x - mu2[g]) * sc + b2s[o];
            float z1 = (yf.y - mu2[g]) * sc + b2s[o];
            z0 = z0 * fsig(z0);
            z1 = z1 * fsig(z1);
#pragma unroll
            for (int h = 0; h < 8; h++) {
                float w = wrd[h * 24 + o];
                r0[h] += w * z0;
                r1[h] += w * z1;
            }
        }
#pragma unroll
        for (int h = 0; h < 8; h++) {
            R[(size_t)h * 131072 + p] = __floats2half2_rn(r0[h], r1[h]);
            s3 += r0[h] + r1[h];
            q3 += r0[h] * r0[h] + r1[h] * r1[h];
        }
    }
    s3 = wred(s3); q3 = wred(q3);
    if ((t & 31) == 0) { atomicAdd(&red[0], s3); atomicAdd(&red[1], q3); }
    __syncthreads();
    if (t < 2) atomicAdd(&S_stats3[b * 2 + t], red[t]);
}

// ---------------- AV product (GN3 applied on the fly) ----------------
__global__ __launch_bounds__(256) void k_av(const float* __restrict__ g3, const float* __restrict__ b3) {
    const int bh = blockIdx.x;
    const int n0 = blockIdx.y * 32;
    const int b = bh >> 3, h = bh & 7;
    extern __shared__ float sm[];
    float* vs = sm;          // 8192
    float* rs = sm + 8192;   // 8192
    __shared__ float params[2];
    if (threadIdx.x == 0) {
        const float cnt = 2097152.f;
        float s = S_stats3[b * 2], qq = S_stats3[b * 2 + 1];
        float m = s / cnt;
        float rstd = rsqrtf(qq / cnt - m * m + EPS_);
        float gh = g3[h];
        params[0] = rstd * gh;
        params[1] = b3[h] - m * rstd * gh;
    }
    __syncthreads();
    float scl = params[0], sft = params[1];
    for (int idx = threadIdx.x; idx < 8192; idx += 256)
        vs[idx] = S_v[(size_t)bh * 8192 + idx];
    const __half2* R = (const __half2*)S_r + (size_t)(bh * 1024 + n0) * 128;
    for (int idx = threadIdx.x; idx < 4096; idx += 256) {
        float2 f = __half22float2(R[idx]);
        float2 w = make_float2(f.x * scl + sft, f.y * scl + sft);
        *(float2*)&rs[2 * idx] = w;
    }
    __syncthreads();
    const int d = threadIdx.x & 31, nb = threadIdx.x >> 5;
    float acc[4];
#pragma unroll
    for (int k = 0; k < 4; k++) acc[k] = 0.f;
    for (int m = 0; m < 256; m += 4) {
        float v0 = vs[m * 32 + d];
        float v1 = vs[(m + 1) * 32 + d];
        float v2 = vs[(m + 2) * 32 + d];
        float v3 = vs[(m + 3) * 32 + d];
#pragma unroll
        for (int k = 0; k < 4; k++) {
            int nl = nb + k * 8;
            float4 rr = *(const float4*)(rs + nl * 256 + m);
            acc[k] += rr.x * v0 + rr.y * v1 + rr.z * v2 + rr.w * v3;
        }
    }
#pragma unroll
    for (int k = 0; k < 4; k++) {
        int nl = nb + k * 8;
        S_hout[(size_t)(b * 1024 + n0 + nl) * 256 + h * 32 + d] = acc[k];
    }
}

// ---------------- output projection + NCHW transpose ----------------
__global__ __launch_bounds__(256) void k_out(const float* __restrict__ Wp, const float* __restrict__ bp,
                                             float* __restrict__ out) {
    const int b = blockIdx.x;
    const int n0 = blockIdx.y * 32;
    extern __shared__ float sm2[];  // 256*36 floats
    float* hs = sm2;
    for (int idx = threadIdx.x; idx < 8192; idx += 256) {
        int nl = idx >> 8, cp = idx & 255;
        hs[cp * 36 + nl] = S_hout[(size_t)(b * 1024 + n0 + nl) * 256 + cp];
    }
    __syncthreads();
    int c = threadIdx.x;
    float acc[32];
#pragma unroll
    for (int i = 0; i < 32; i++) acc[i] = 0.f;
    const float* wrow = Wp + c * 256;
    for (int cp = 0; cp < 256; cp++) {
        float w = __ldg(wrow + cp);
        const float4* h4 = (const float4*)(hs + cp * 36);
#pragma unroll
        for (int i4 = 0; i4 < 8; i4++) {
            float4 hh = h4[i4];
            acc[i4 * 4 + 0] += hh.x * w;
            acc[i4 * 4 + 1] += hh.y * w;
            acc[i4 * 4 + 2] += hh.z * w;
            acc[i4 * 4 + 3] += hh.w * w;
        }
    }
    float bpc = bp[c];
    __syncthreads();
    float* os = sm2;
#pragma unroll
    for (int i = 0; i < 32; i++) os[c * 36 + i] = acc[i] + bpc;
    __syncthreads();
    for (int idx = threadIdx.x; idx < 8192; idx += 256) {
        int c2 = idx >> 5, i2 = idx & 31;
        out[((size_t)b * 256 + c2) * 1024 + n0 + i2] = os[c2 * 36 + i2];
    }
}

// ---------------- host launcher ----------------
extern "C" void kernel_launch(void* const* d_in, const int* in_sizes, int n_in,
                              void* d_out, int out_size) {
    const float* q     = (const float*)d_in[0];
    const float* kv    = (const float*)d_in[1];
    const float* Wq    = (const float*)d_in[2];
    const float* Wkv   = (const float*)d_in[3];
    const float* Wp    = (const float*)d_in[4];
    const float* bp    = (const float*)d_in[5];
    const float* rpb   = (const float*)d_in[6];
    const float* W_exp = (const float*)d_in[7];
    const float* g1    = (const float*)d_in[8];
    const float* b1    = (const float*)d_in[9];
    const float* W_dw  = (const float*)d_in[10];
    const float* g2    = (const float*)d_in[11];
    const float* b2    = (const float*)d_in[12];
    const float* W_red = (const float*)d_in[13];
    const float* g3    = (const float*)d_in[14];
    const float* b3    = (const float*)d_in[15];
    float* out = (float*)d_out;

    cudaFuncSetAttribute(k_dla0, cudaFuncAttributeMaxDynamicSharedMemorySize, 24 * 612 * 4);
    cudaFuncSetAttribute(k_av, cudaFuncAttributeMaxDynamicSharedMemorySize, 65536);
    cudaFuncSetAttribute(k_out, cudaFuncAttributeMaxDynamicSharedMemorySize, 256 * 36 * 4);

    k_all_proj<<<dim3(16, 48), 256>>>(q, Wq, kv, Wkv);
    k_attn<<<dim3(128, 16), 256>>>(rpb);
    k_stats1<<<dim3(16, 32), 256>>>(W_exp);
    k_dla0<<<dim3(8, 64, 16), 256, 24 * 612 * 4>>>(W_exp, g1, b1, W_dw);
    k_red<<<dim3(16, 128), 256>>>(g2, b2, W_red);
    k_av<<<dim3(128, 32), 256, 65536>>>(g3, b3);
    k_out<<<dim3(16, 32), 256, 256 * 36 * 4>>>(Wp, bp, out);
}

// round 5
// speedup vs baseline: 1.3909x; 1.3909x over previous
#include <cuda_runtime.h>
#include <math.h>

// Problem constants
#define B_   16
#define C_   256
#define NH_  8
#define HD_  32
#define N_   1024
#define M_   256
#define HID_ 24
#define EPS_ 1e-5f

// ---------------- scratch (static __device__, no allocs) ----------------
__device__ float S_q[B_ * NH_ * N_ * HD_];
__device__ float S_k[B_ * NH_ * M_ * HD_];
__device__ float S_v[B_ * NH_ * M_ * HD_];
__device__ float S_attn[B_ * NH_ * N_ * M_];   // 134 MB
__device__ float S_y[B_ * HID_ * N_ * M_];     // 403 MB
__device__ float S_r[B_ * NH_ * N_ * M_];      // 134 MB
__device__ float S_hout[B_ * N_ * C_];
__device__ float S_gram[B_ * 36];
__device__ float S_stats1[B_ * 3 * 2];
__device__ float S_stats2[B_ * 3 * 2];
__device__ float S_stats3[B_ * 2];

__device__ __forceinline__ float wred(float v) {
#pragma unroll
    for (int o = 16; o; o >>= 1) v += __shfl_xor_sync(0xffffffffu, v, o);
    return v;
}
__device__ __forceinline__ float tanh_fast(float x) {
    float y;
    asm("tanh.approx.f32 %0, %1;" : "=f"(y) : "f"(x));
    return y;
}
// swish(x) = x * sigmoid(x) = 0.5*x*(1 + tanh(0.5*x))  -- single MUFU op
__device__ __forceinline__ float fswish(float x) {
    return 0.5f * x * (1.f + tanh_fast(0.5f * x));
}

// ---------------- fused projections (q + kv) + scratch zeroing ----------------
__global__ __launch_bounds__(256) void k_all_proj(
    const float* __restrict__ q, const float* __restrict__ Wq,
    const float* __restrict__ kv, const float* __restrict__ Wkv) {
    __shared__ float sbuf[8192];
    const int b = blockIdx.x;
    const int y = blockIdx.y;
    const int t = threadIdx.x;
    if (b == 0 && y == 0) {
        for (int i = t; i < 576; i += 256) S_gram[i] = 0.f;
        if (t < 96) S_stats2[t] = 0.f;
        if (t < 32) S_stats3[t] = 0.f;
    }
    if (y < 32) {
        const int n0 = y * 32;
        for (int idx = t; idx < 2048; idx += 256) {
            int c = idx >> 3, i4 = idx & 7;
            ((float4*)sbuf)[idx] = ((const float4*)(q + (b * 256 + c) * 1024 + n0))[i4];
        }
        __syncthreads();
        float acc[32];
#pragma unroll
        for (int i = 0; i < 32; i++) acc[i] = 0.f;
        const float* wrow = Wq + t * 256;
        for (int c = 0; c < 256; c++) {
            float w = __ldg(wrow + c);
            const float4* q4 = (const float4*)(sbuf + c * 32);
#pragma unroll
            for (int i4 = 0; i4 < 8; i4++) {
                float4 qq = q4[i4];
                acc[i4 * 4 + 0] += qq.x * w;
                acc[i4 * 4 + 1] += qq.y * w;
                acc[i4 * 4 + 2] += qq.z * w;
                acc[i4 * 4 + 3] += qq.w * w;
            }
        }
        int h = t >> 5, d = t & 31;
#pragma unroll
        for (int i = 0; i < 32; i++)
            S_q[((b * 8 + h) * 1024 + n0 + i) * 32 + d] = acc[i];
    } else {
        const int m0 = (y - 32) * 16;
        for (int idx = t; idx < 4096; idx += 256) {
            int c = idx >> 4, i = idx & 15;
            sbuf[c * 16 + i] = kv[(b * 256 + c) * 256 + m0 + i];
        }
        __syncthreads();
        for (int jj = 0; jj < 2; jj++) {
            int j = t + jj * 256;
            float acc[16];
#pragma unroll
            for (int i = 0; i < 16; i++) acc[i] = 0.f;
            const float* wrow = Wkv + j * 256;
            for (int c = 0; c < 256; c++) {
                float w = __ldg(wrow + c);
                const float4* k4 = (const float4*)(sbuf + c * 16);
#pragma unroll
                for (int i4 = 0; i4 < 4; i4++) {
                    float4 kk = k4[i4];
                    acc[i4 * 4 + 0] += kk.x * w;
                    acc[i4 * 4 + 1] += kk.y * w;
                    acc[i4 * 4 + 2] += kk.z * w;
                    acc[i4 * 4 + 3] += kk.w * w;
                }
            }
            float* dst = (j < 256) ? S_k : S_v;
            int hd = j & 255;
            int h = hd >> 5, d = hd & 31;
#pragma unroll
            for (int i = 0; i < 16; i++)
                dst[((b * 8 + h) * 256 + m0 + i) * 32 + d] = acc[i];
        }
    }
}

// ---------------- attention: register-tiled QK^T + softmax (fp32 out) ----------------
__global__ __launch_bounds__(256) void k_attn(const float* __restrict__ rpb) {
    const int bh = blockIdx.x;
    const int n0 = blockIdx.y * 64;
    __shared__ float Qs[32 * 68];
    __shared__ float Ks[32 * 260];
    const int t = threadIdx.x;
    {
        const int d = t & 31, g = t >> 5;
        const float* qsrc = S_q + (size_t)(bh * 1024 + n0) * 32 + d;
#pragma unroll
        for (int i = 0; i < 8; i++)
            Qs[d * 68 + g * 8 + i] = qsrc[(g * 8 + i) * 32];
        const float* ksrc = S_k + (size_t)bh * 8192 + d;
#pragma unroll
        for (int i = 0; i < 32; i++)
            Ks[d * 260 + g * 32 + i] = ksrc[(g * 32 + i) * 32];
    }
    __syncthreads();
    const int mg = t & 31;
    const int ng = t >> 5;
    float acc[8][8];
#pragma unroll
    for (int i = 0; i < 8; i++)
#pragma unroll
        for (int j = 0; j < 8; j++) acc[i][j] = 0.f;
#pragma unroll 4
    for (int k = 0; k < 32; k++) {
        float4 q0 = *(const float4*)&Qs[k * 68 + ng * 8];
        float4 q1 = *(const float4*)&Qs[k * 68 + ng * 8 + 4];
        float4 k0 = *(const float4*)&Ks[k * 260 + mg * 8];
        float4 k1 = *(const float4*)&Ks[k * 260 + mg * 8 + 4];
        float qv[8] = {q0.x, q0.y, q0.z, q0.w, q1.x, q1.y, q1.z, q1.w};
        float kw[8] = {k0.x, k0.y, k0.z, k0.w, k1.x, k1.y, k1.z, k1.w};
#pragma unroll
        for (int i = 0; i < 8; i++)
#pragma unroll
            for (int j = 0; j < 8; j++) acc[i][j] += qv[i] * kw[j];
    }
    const float scale = 0.17677669529663689f;
#pragma unroll
    for (int i = 0; i < 8; i++) {
        const int n = n0 + ng * 8 + i;
        const float* rp = rpb + (size_t)n * 256 + mg * 8;
        float4 r0 = *(const float4*)rp;
        float4 r1 = *(const float4*)(rp + 4);
        float rb[8] = {r0.x, r0.y, r0.z, r0.w, r1.x, r1.y, r1.z, r1.w};
        float mx = -1e30f;
#pragma unroll
        for (int j = 0; j < 8; j++) {
            acc[i][j] = acc[i][j] * scale + rb[j];
            mx = fmaxf(mx, acc[i][j]);
        }
#pragma unroll
        for (int o = 16; o; o >>= 1) mx = fmaxf(mx, __shfl_xor_sync(0xffffffffu, mx, o));
        float s = 0.f;
#pragma unroll
        for (int j = 0; j < 8; j++) {
            float e = __expf(acc[i][j] - mx);
            acc[i][j] = e;
            s += e;
        }
        s = wred(s);
        float inv = __fdividef(1.f, s);
        float* dst = S_attn + (size_t)(bh * 1024 + n) * 256 + mg * 8;
        float4 o0 = make_float4(acc[i][0] * inv, acc[i][1] * inv, acc[i][2] * inv, acc[i][3] * inv);
        float4 o1 = make_float4(acc[i][4] * inv, acc[i][5] * inv, acc[i][6] * inv, acc[i][7] * inv);
        *(float4*)dst = o0;
        *(float4*)(dst + 4) = o1;
    }
}

// ---------------- head Gram matrix: G[b,i,j] = <A_i, A_j> (36 upper-tri) ----------------
__global__ __launch_bounds__(256) void k_gram() {
    const int b = blockIdx.x;
    const int base = blockIdx.y * 8192 + threadIdx.x;
    __shared__ float gs[36];
    const int t = threadIdx.x;
    if (t < 36) gs[t] = 0.f;
    __syncthreads();
    float g[36];
#pragma unroll
    for (int c = 0; c < 36; c++) g[c] = 0.f;
    const float* A = S_attn + (size_t)b * 2097152;
#pragma unroll 1
    for (int k = 0; k < 32; k++) {
        int pix = base + k * 256;
        float a[8];
#pragma unroll
        for (int h = 0; h < 8; h++) a[h] = A[h * 262144 + pix];
        int c = 0;
#pragma unroll
        for (int i = 0; i < 8; i++)
#pragma unroll
            for (int j = i; j < 8; j++) g[c++] += a[i] * a[j];
    }
#pragma unroll
    for (int c = 0; c < 36; c++) {
        g[c] = wred(g[c]);
        if ((t & 31) == 0) atomicAdd(&gs[c], g[c]);
    }
    __syncthreads();
    if (t < 36) atomicAdd(&S_gram[b * 36 + t], gs[t]);
}

// ---------------- derive GN1 stats analytically from G and W_exp ----------------
__global__ void k_stats1p(const float* __restrict__ W_exp) {
    const int t = threadIdx.x;
    if (t >= 48) return;
    const int b = t / 3, g = t % 3;
    float sumw = 0.f, sumxx = 0.f;
    const float* G = S_gram + b * 36;
    for (int o = g * 8; o < g * 8 + 8; o++) {
        float wo[8];
#pragma unroll
        for (int h = 0; h < 8; h++) wo[h] = W_exp[o * 8 + h];
#pragma unroll
        for (int h = 0; h < 8; h++) sumw += wo[h];
#pragma unroll
        for (int i = 0; i < 8; i++)
#pragma unroll
            for (int j = 0; j < 8; j++) {
                int a = i < j ? i : j, bb = i < j ? j : i;
                sumxx += wo[i] * wo[j] * G[8 * a - a * (a - 1) / 2 + (bb - a)];
            }
    }
    S_stats1[b * 6 + 2 * g] = sumw * 1024.f;
    S_stats1[b * 6 + 2 * g + 1] = sumxx;
}

// ---------------- DLA pass 0: expand->GN1->swish->dw3x3 -> y + GN2 stats ----------------
__global__ __launch_bounds__(256, 3) void k_dla0(
    const float* __restrict__ W_exp, const float* __restrict__ g1,
    const float* __restrict__ b1, const float* __restrict__ W_dw) {
    const int m0 = blockIdx.x * 32;
    const int n0 = blockIdx.y * 16;
    const int b = blockIdx.z;
    extern __shared__ float xact[];  // 24 * 612 floats
    __shared__ float we[192], wd[216];
    __shared__ float g1s[24], b1s[24];
    __shared__ float mu1[3], rs1[3];
    __shared__ float red[6];
    const int t = threadIdx.x;
    if (t < 192) we[t] = W_exp[t];
    if (t < 216) wd[t] = W_dw[t];
    if (t < 24) { g1s[t] = g1[t]; b1s[t] = b1[t]; }
    if (t < 3) {
        const float cnt = 2097152.f;
        float s = S_stats1[b * 6 + 2 * t], qq = S_stats1[b * 6 + 2 * t + 1];
        float m = s / cnt;
        mu1[t] = m;
        rs1[t] = rsqrtf(qq / cnt - m * m + EPS_);
    }
    if (t < 6) red[t] = 0.f;
    __syncthreads();

    // Phase 1: build activated expand tile (with halo) in smem
#pragma unroll 1
    for (int idx = t; idx < 612; idx += 256) {
        int i = idx / 34, j = idx - i * 34;
        int gi = n0 - 1 + i, gj = m0 - 1 + j;
        if ((unsigned)gi < 1024u && (unsigned)gj < 256u) {
            const float* A = S_attn + (size_t)b * 2097152 + gi * 256 + gj;
            float a[8];
#pragma unroll
            for (int h = 0; h < 8; h++) a[h] = A[h * 262144];
#pragma unroll
            for (int o = 0; o < 24; o++) {
                float x = 0.f;
#pragma unroll
                for (int h = 0; h < 8; h++) x += we[o * 8 + h] * a[h];
                int g = o >> 3;
                x = (x - mu1[g]) * rs1[g] * g1s[o] + b1s[o];
                xact[o * 612 + idx] = fswish(x);
            }
        } else {
#pragma unroll
            for (int o = 0; o < 24; o++) xact[o * 612 + idx] = 0.f;
        }
    }
    __syncthreads();

    // Phase 2: depthwise conv, write y, accumulate GN2 stats
    float s0 = 0, s1 = 0, s2 = 0, q0 = 0, q1 = 0, q2 = 0;
#pragma unroll 1
    for (int k = 0; k < 2; k++) {
        int pixl = t + k * 256;
        int i = pixl >> 5, j = pixl & 31;
        size_t gp = (size_t)(n0 + i) * 256 + (m0 + j);
#pragma unroll
        for (int o = 0; o < 24; o++) {
            const float* xb = xact + o * 612 + i * 34 + j;
            const float* w = wd + o * 9;
            float y = w[0] * xb[0] + w[1] * xb[1] + w[2] * xb[2]
                    + w[3] * xb[34] + w[4] * xb[35] + w[5] * xb[36]
                    + w[6] * xb[68] + w[7] * xb[69] + w[8] * xb[70];
            S_y[((size_t)(b * 24 + o)) * 262144 + gp] = y;
            if (o < 8)       { s0 += y; q0 += y * y; }
            else if (o < 16) { s1 += y; q1 += y * y; }
            else             { s2 += y; q2 += y * y; }
        }
    }
    s0 = wred(s0); q0 = wred(q0); s1 = wred(s1);
    q1 = wred(q1); s2 = wred(s2); q2 = wred(q2);
    if ((t & 31) == 0) {
        atomicAdd(&red[0], s0); atomicAdd(&red[1], q0);
        atomicAdd(&red[2], s1); atomicAdd(&red[3], q1);
        atomicAdd(&red[4], s2); atomicAdd(&red[5], q2);
    }
    __syncthreads();
    if (t < 6) atomicAdd(&S_stats2[b * 6 + t], red[t]);
}

// ---------------- DLA pass 1: GN2->swish->1x1 reduce -> r + GN3 stats ----------------
__global__ __launch_bounds__(256) void k_red(
    const float* __restrict__ g2, const float* __restrict__ b2,
    const float* __restrict__ W_red) {
    const int b = blockIdx.x;
    const int pix0 = blockIdx.y * 2048;
    __shared__ float wrd[192], g2s[24], b2s[24];
    __shared__ float mu2[3], rs2[3];
    __shared__ float red[2];
    const int t = threadIdx.x;
    if (t < 192) wrd[t] = W_red[t];
    if (t < 24) { g2s[t] = g2[t]; b2s[t] = b2[t]; }
    if (t < 3) {
        const float cnt = 2097152.f;
        float s = S_stats2[b * 6 + 2 * t], qq = S_stats2[b * 6 + 2 * t + 1];
        float m = s / cnt;
        mu2[t] = m;
        rs2[t] = rsqrtf(qq / cnt - m * m + EPS_);
    }
    if (t < 2) red[t] = 0.f;
    __syncthreads();
    float s3 = 0, q3 = 0;
    const float* Y = S_y + (size_t)b * 24 * 262144;
    float* R = S_r + (size_t)b * 8 * 262144;
#pragma unroll 1
    for (int k = 0; k < 8; k++) {
        int pix = pix0 + k * 256 + t;
        float r[8];
#pragma unroll
        for (int h = 0; h < 8; h++) r[h] = 0.f;
#pragma unroll
        for (int o = 0; o < 24; o++) {
            float y = Y[(size_t)o * 262144 + pix];
            int g = o >> 3;
            float z = (y - mu2[g]) * rs2[g] * g2s[o] + b2s[o];
            z = fswish(z);
#pragma unroll
            for (int h = 0; h < 8; h++) r[h] += wrd[h * 24 + o] * z;
        }
#pragma unroll
        for (int h = 0; h < 8; h++) {
            R[(size_t)h * 262144 + pix] = r[h];
            s3 += r[h];
            q3 += r[h] * r[h];
        }
    }
    s3 = wred(s3); q3 = wred(q3);
    if ((t & 31) == 0) { atomicAdd(&red[0], s3); atomicAdd(&red[1], q3); }
    __syncthreads();
    if (t < 2) atomicAdd(&S_stats3[b * 2 + t], red[t]);
}

// ---------------- AV product (GN3 applied on the fly) ----------------
__global__ __launch_bounds__(256) void k_av(const float* __restrict__ g3, const float* __restrict__ b3) {
    const int bh = blockIdx.x;
    const int n0 = blockIdx.y * 32;
    const int b = bh >> 3, h = bh & 7;
    extern __shared__ float sm[];
    float* vs = sm;          // 8192
    float* rs = sm + 8192;   // 8192
    __shared__ float params[2];
    if (threadIdx.x == 0) {
        const float cnt = 2097152.f;
        float s = S_stats3[b * 2], qq = S_stats3[b * 2 + 1];
        float m = s / cnt;
        float rstd = rsqrtf(qq / cnt - m * m + EPS_);
        float gh = g3[h];
        params[0] = rstd * gh;
        params[1] = b3[h] - m * rstd * gh;
    }
    __syncthreads();
    float scl = params[0], sft = params[1];
    for (int idx = threadIdx.x; idx < 8192; idx += 256)
        vs[idx] = S_v[(size_t)bh * 8192 + idx];
    const float* R = S_r + (size_t)(bh * 1024 + n0) * 256;
    for (int idx = threadIdx.x; idx < 8192; idx += 256)
        rs[idx] = R[idx] * scl + sft;
    __syncthreads();
    const int d = threadIdx.x & 31, nb = threadIdx.x >> 5;
    float acc[4];
#pragma unroll
    for (int k = 0; k < 4; k++) acc[k] = 0.f;
    for (int m = 0; m < 256; m += 4) {
        float v0 = vs[m * 32 + d];
        float v1 = vs[(m + 1) * 32 + d];
        float v2 = vs[(m + 2) * 32 + d];
        float v3 = vs[(m + 3) * 32 + d];
#pragma unroll
        for (int k = 0; k < 4; k++) {
            int nl = nb + k * 8;
            float4 rr = *(const float4*)(rs + nl * 256 + m);
            acc[k] += rr.x * v0 + rr.y * v1 + rr.z * v2 + rr.w * v3;
        }
    }
#pragma unroll
    for (int k = 0; k < 4; k++) {
        int nl = nb + k * 8;
        S_hout[(size_t)(b * 1024 + n0 + nl) * 256 + h * 32 + d] = acc[k];
    }
}

// ---------------- output projection + NCHW transpose ----------------
__global__ __launch_bounds__(256) void k_out(const float* __restrict__ Wp, const float* __restrict__ bp,
                                             float* __restrict__ out) {
    const int b = blockIdx.x;
    const int n0 = blockIdx.y * 32;
    extern __shared__ float sm2[];  // 256*36 floats
    float* hs = sm2;
    for (int idx = threadIdx.x; idx < 8192; idx += 256) {
        int nl = idx >> 8, cp = idx & 255;
        hs[cp * 36 + nl] = S_hout[(size_t)(b * 1024 + n0 + nl) * 256 + cp];
    }
    __syncthreads();
    int c = threadIdx.x;
    float acc[32];
#pragma unroll
    for (int i = 0; i < 32; i++) acc[i] = 0.f;
    const float* wrow = Wp + c * 256;
    for (int cp = 0; cp < 256; cp++) {
        float w = __ldg(wrow + cp);
        const float4* h4 = (const float4*)(hs + cp * 36);
#pragma unroll
        for (int i4 = 0; i4 < 8; i4++) {
            float4 hh = h4[i4];
            acc[i4 * 4 + 0] += hh.x * w;
            acc[i4 * 4 + 1] += hh.y * w;
            acc[i4 * 4 + 2] += hh.z * w;
            acc[i4 * 4 + 3] += hh.w * w;
        }
    }
    float bpc = bp[c];
    __syncthreads();
    float* os = sm2;
#pragma unroll
    for (int i = 0; i < 32; i++) os[c * 36 + i] = acc[i] + bpc;
    __syncthreads();
    for (int idx = threadIdx.x; idx < 8192; idx += 256) {
        int c2 = idx >> 5, i2 = idx & 31;
        out[((size_t)b * 256 + c2) * 1024 + n0 + i2] = os[c2 * 36 + i2];
    }
}

// ---------------- host launcher ----------------
extern "C" void kernel_launch(void* const* d_in, const int* in_sizes, int n_in,
                              void* d_out, int out_size) {
    const float* q     = (const float*)d_in[0];
    const float* kv    = (const float*)d_in[1];
    const float* Wq    = (const float*)d_in[2];
    const float* Wkv   = (const float*)d_in[3];
    const float* Wp    = (const float*)d_in[4];
    const float* bp    = (const float*)d_in[5];
    const float* rpb   = (const float*)d_in[6];
    const float* W_exp = (const float*)d_in[7];
    const float* g1    = (const float*)d_in[8];
    const float* b1    = (const float*)d_in[9];
    const float* W_dw  = (const float*)d_in[10];
    const float* g2    = (const float*)d_in[11];
    const float* b2    = (const float*)d_in[12];
    const float* W_red = (const float*)d_in[13];
    const float* g3    = (const float*)d_in[14];
    const float* b3    = (const float*)d_in[15];
    float* out = (float*)d_out;

    cudaFuncSetAttribute(k_dla0, cudaFuncAttributeMaxDynamicSharedMemorySize, 24 * 612 * 4);
    cudaFuncSetAttribute(k_av, cudaFuncAttributeMaxDynamicSharedMemorySize, 65536);
    cudaFuncSetAttribute(k_out, cudaFuncAttributeMaxDynamicSharedMemorySize, 256 * 36 * 4);

    k_all_proj<<<dim3(16, 48), 256>>>(q, Wq, kv, Wkv);
    k_attn<<<dim3(128, 16), 256>>>(rpb);
    k_gram<<<dim3(16, 32), 256>>>();
    k_stats1p<<<1, 64>>>(W_exp);
    k_dla0<<<dim3(8, 64, 16), 256, 24 * 612 * 4>>>(W_exp, g1, b1, W_dw);
    k_red<<<dim3(16, 128), 256>>>(g2, b2, W_red);
    k_av<<<dim3(128, 32), 256, 65536>>>(g3, b3);
    k_out<<<dim3(16, 32), 256, 256 * 36 * 4>>>(Wp, bp, out);
}